// round 5
// baseline (speedup 1.0000x reference)
#include <cuda_runtime.h>
#include <cstdint>
#include <math.h>

// Problem constants (fixed by the reference)
#define T_STEPS 250
#define NCH     3
#define DFEAT   40
#define IN_DIM  120     // NCH*DFEAT
#define NHID    200
#define NHPAD   208     // spike array padded so readout float4 never OOB
#define NBR     8
#define NBRT    4       // branches per thread (2 threads per neuron)
#define PER     15      // IN_DIM / NBR
#define PERP    16      // padded per-branch stride in xbuf
#define XPAD    (NBR*PERP)   // 128
#define ODIM    35
#define NB      4       // batch elements per CTA
#define RCH     16      // readout chunk (neurons per part)
#define RPARTS  13      // ceil(208/16)
#define THREADS 512

// branch k -> xbuf slot: interleave so even-lane (k<4) and odd-lane (k>=4)
// addresses in the same warp-instruction land in disjoint bank groups.
#define BSLOT(k) (2 * ((k) & 3) + ((k) >> 2))

// ---------------- packed f32x2 helpers (sm_100a) ----------------
__device__ __forceinline__ unsigned long long ffma2(unsigned long long a,
                                                    unsigned long long b,
                                                    unsigned long long c) {
    unsigned long long d;
    asm("fma.rn.f32x2 %0, %1, %2, %3;" : "=l"(d) : "l"(a), "l"(b), "l"(c));
    return d;
}
__device__ __forceinline__ unsigned long long add2(unsigned long long a,
                                                   unsigned long long b) {
    unsigned long long d;
    asm("add.rn.f32x2 %0, %1, %2;" : "=l"(d) : "l"(a), "l"(b));
    return d;
}
__device__ __forceinline__ unsigned long long pack2(float lo, float hi) {
    unsigned long long u;
    asm("mov.b64 %0, {%1, %2};" : "=l"(u) : "f"(lo), "f"(hi));
    return u;
}
__device__ __forceinline__ float2 unpack2(unsigned long long u) {
    float lo, hi;
    asm("mov.b64 {%0, %1}, %2;" : "=f"(lo), "=f"(hi) : "l"(u));
    return make_float2(lo, hi);
}
__device__ __forceinline__ float sigmoid_acc(float v) {
    return 1.0f / (1.0f + expf(-v));
}

// One CTA = NB=4 batch elements; 512 threads; 2 threads per neuron (branch
// halves combined via shfl). Register state per thread ~125 -> no spilling
// at the 128-reg/thread budget of a 512-thread CTA. Grid = 128 = one wave.
__global__ void __launch_bounds__(THREADS, 1) snn_kernel(
    const float* __restrict__ x,       // [B, 3, 250, 40]
    const float* __restrict__ W1,      // [200, 8, 120]
    const float* __restrict__ b1,      // [200]
    const float* __restrict__ tau_m1,  // [200]
    const float* __restrict__ tau_n1,  // [200, 8]
    const float* __restrict__ W2,      // [35, 200]
    const float* __restrict__ b2,      // [35]
    const float* __restrict__ tau_m2,  // [35]
    float* __restrict__ out,           // [B, 35]
    int B)
{
    __shared__ __align__(16) float xbuf[NB][XPAD];       // slot-interleaved xt
    __shared__ __align__(16) float spk_s[NB][NHPAD];     // spikes (tail zero)
    __shared__ float psum[RPARTS][NB][ODIM + 1];         // readout partials
    __shared__ float accbuf[NB][ODIM];                   // log-softmax staging

    const int tid = threadIdx.x;
    const int b0  = blockIdx.x * NB;

    // ---------- one-time SMEM zeroing (spike tail + xbuf pads) ----------
    if (tid < NB * 8) spk_s[tid / 8][NHID + (tid % 8)] = 0.0f;   // 200..207
    if (tid >= 32 && tid < 32 + NB * 8) {
        const int idx = tid - 32;
        xbuf[idx / 8][(idx % 8) * PERP + PER] = 0.0f;            // pad j=15
    }

    // ============ neuron-role init: tid<416 (warps 0..12 full) ============
    const int h   = tid & 1;                 // branch-half
    const int nn0 = tid >> 1;                // neuron id (valid if < 200)
    const int ncl = (nn0 < NHID) ? nn0 : NHID - 1;
    unsigned long long wp[NBRT * 7];
    float w14[NBRT], beta[NBRT];
    float dst[NB][NBRT];
    float mem1[NB], spk[NB];
    float alpha1 = 0.f, oma1 = 0.f, b1n = 0.f;
#pragma unroll
    for (int bl = 0; bl < NB; bl++) {
        mem1[bl] = 0.f; spk[bl] = 0.f;
#pragma unroll
        for (int kk = 0; kk < NBRT; kk++) dst[bl][kk] = 0.f;
    }
    if (tid < 416) {
        alpha1 = sigmoid_acc(tau_m1[ncl]);
        oma1   = 1.0f - alpha1;
        b1n    = b1[ncl];
#pragma unroll
        for (int kk = 0; kk < NBRT; kk++) {
            const int k = 4 * h + kk;
            beta[kk] = sigmoid_acc(tau_n1[ncl * NBR + k]);
            const float* wrow = W1 + (size_t)(ncl * NBR + k) * IN_DIM + k * PER;
#pragma unroll
            for (int j = 0; j < 7; j++)
                wp[kk * 7 + j] = pack2(wrow[2 * j], wrow[2 * j + 1]);
            w14[kk] = wrow[14];
        }
    } else {
#pragma unroll
        for (int m = 0; m < NBRT * 7; m++) wp[m] = 0ull;
#pragma unroll
        for (int kk = 0; kk < NBRT; kk++) { beta[kk] = 0.f; w14[kk] = 0.f; }
    }

    // ============ readout role: tid<455, part p chunk of 16 neurons ============
    const int p_ro = tid / ODIM;             // 0..12
    const int o_ro = tid % ODIM;
    const int np0  = p_ro * RCH;             // 16p, 64B-aligned in spk_s
    float w2r[RCH];
#pragma unroll
    for (int j = 0; j < RCH; j++) w2r[j] = 0.f;
    if (tid < RPARTS * ODIM) {
        for (int j = 0; j < RCH; j++)
            if (np0 + j < NHID) w2r[j] = W2[o_ro * NHID + np0 + j];
    }

    // ============ integrator role: tid<140 ============
    float alpha2 = 0.f, oma2 = 0.f, b2o = 0.f, mem2 = 0.f, acc = 0.f;
    if (tid < NB * ODIM) {
        alpha2 = sigmoid_acc(tau_m2[o_ro]);
        oma2   = 1.0f - alpha2;
        b2o    = b2[o_ro];
    }

    // ============ x prefetch: 480 threads x 1 float ============
    const float* pf_ptr = nullptr;
    float*       slw    = nullptr;
    float xr = 0.f;
    if (tid < NB * IN_DIM) {
        const int blp = tid / IN_DIM;
        const int i0  = tid % IN_DIM;
        const int c   = i0 / DFEAT;
        const int d   = i0 % DFEAT;
        int bb = b0 + blp; if (bb > B - 1) bb = B - 1;
        pf_ptr = x + ((size_t)bb * NCH + c) * T_STEPS * DFEAT + d;
        slw = &xbuf[blp][BSLOT(i0 / PER) * PERP + (i0 % PER)];
        xr  = *pf_ptr;                     // t = 0
    }

    __syncthreads();

    // ============================ time loop ============================
#pragma unroll 1
    for (int t = 0; t < T_STEPS; t++) {
        if (pf_ptr) *slw = xr;             // scatter xt
        __syncthreads();                   // S1

        if (pf_ptr) {                      // prefetch t+1
            const int tn = (t + 1 < T_STEPS) ? t + 1 : t;
            xr = pf_ptr[(size_t)tn * DFEAT];
        }

        // ---- neuron phase: 2 threads per neuron, 4 branches each ----
        if (tid < 416) {
#pragma unroll
            for (int bl = 0; bl < NB; bl++) {
                float lh = 0.f;
#pragma unroll
                for (int kk = 0; kk < NBRT; kk++) {
                    // slot = 2*kk + h: even lanes / odd lanes hit disjoint banks
                    const ulonglong2* xp =
                        (const ulonglong2*)(&xbuf[bl][(2 * kk + h) * PERP]);
                    ulonglong2 q0 = xp[0];
                    ulonglong2 q1 = xp[1];
                    unsigned long long a0, a1;
                    a0 = ffma2(wp[kk * 7 + 0], q0.x, 0ull);
                    a1 = ffma2(wp[kk * 7 + 1], q0.y, 0ull);
                    a0 = ffma2(wp[kk * 7 + 2], q1.x, a0);
                    a1 = ffma2(wp[kk * 7 + 3], q1.y, a1);
                    ulonglong2 q2 = xp[2];
                    a0 = ffma2(wp[kk * 7 + 4], q2.x, a0);
                    a1 = ffma2(wp[kk * 7 + 5], q2.y, a1);
                    ulonglong2 q3 = xp[3];
                    a0 = ffma2(wp[kk * 7 + 6], q3.x, a0);
                    float2 vv = unpack2(add2(a0, a1));
                    float2 hx = unpack2(q3.y);           // (x14, 0)
                    float  I  = fmaf(w14[kk], hx.x, vv.x + vv.y);
                    float  dk = dst[bl][kk];
                    dk = fmaf(beta[kk], dk - I, I);
                    dst[bl][kk] = dk;
                    lh += dk;
                }
                // combine halves (lane-adjacent pair, warps 0..12 converged)
                const float l = lh + __shfl_xor_sync(0xFFFFFFFFu, lh, 1) + b1n;
                float m = fmaf(alpha1, mem1[bl] - spk[bl], oma1 * l);
                mem1[bl] = m;
                float s = (m > 1.0f) ? 1.0f : 0.0f;
                spk[bl] = s;
                if (h == 0 && nn0 < NHID) spk_s[bl][nn0] = s;
            }
        }
        __syncthreads();                   // S2: spikes visible

        // ---- readout partials: 13 parts x 35 outputs, W2 in registers ----
        if (tid < RPARTS * ODIM) {
#pragma unroll
            for (int bl = 0; bl < NB; bl++) {
                const float4* sp = (const float4*)(&spk_s[bl][np0]);
                float s0 = 0.f, s1 = 0.f;
#pragma unroll
                for (int q = 0; q < 4; q++) {
                    float4 v = sp[q];
                    s0 = fmaf(v.x, w2r[4 * q + 0], s0);
                    s1 = fmaf(v.y, w2r[4 * q + 1], s1);
                    s0 = fmaf(v.z, w2r[4 * q + 2], s0);
                    s1 = fmaf(v.w, w2r[4 * q + 3], s1);
                }
                psum[p_ro][bl][o_ro] = s0 + s1;
            }
        }
        __syncthreads();                   // S3: partials visible

        // ---- leaky readout integrator: thread (bl, o) ----
        if (tid < NB * ODIM) {
            const int bl = tid / ODIM;
            float z = b2o;
#pragma unroll
            for (int p = 0; p < RPARTS; p++) z += psum[p][bl][o_ro];
            mem2 = fmaf(alpha2, mem2, oma2 * z);
            acc += mem2;
        }
    }

    // ==================== epilogue: log_softmax(acc/T) ====================
    if (tid < NB * ODIM) accbuf[tid / ODIM][o_ro] = acc * (1.0f / (float)T_STEPS);
    __syncthreads();
    if (tid < NB * ODIM) {
        const int bl = tid / ODIM;
        const int b  = b0 + bl;
        if (b < B) {
            float m = -INFINITY;
#pragma unroll
            for (int o = 0; o < ODIM; o++) m = fmaxf(m, accbuf[bl][o]);
            float ssum = 0.0f;
#pragma unroll
            for (int o = 0; o < ODIM; o++) ssum += expf(accbuf[bl][o] - m);
            out[(size_t)b * ODIM + o_ro] = accbuf[bl][o_ro] - m - logf(ssum);
        }
    }
}

extern "C" void kernel_launch(void* const* d_in, const int* in_sizes, int n_in,
                              void* d_out, int out_size) {
    const float* x      = (const float*)d_in[0];
    const float* W1     = (const float*)d_in[1];
    const float* b1     = (const float*)d_in[2];
    const float* tau_m1 = (const float*)d_in[3];
    const float* tau_n1 = (const float*)d_in[4];
    const float* W2     = (const float*)d_in[5];
    const float* b2     = (const float*)d_in[6];
    const float* tau_m2 = (const float*)d_in[7];
    float* out = (float*)d_out;

    const int B = in_sizes[0] / (NCH * T_STEPS * DFEAT);   // 512
    const int grid = (B + NB - 1) / NB;                    // 128
    snn_kernel<<<grid, THREADS>>>(x, W1, b1, tau_m1, tau_n1, W2, b2, tau_m2,
                                  out, B);
}